// round 7
// baseline (speedup 1.0000x reference)
#include <cuda_runtime.h>
#include <cstdint>

// VectorQuantizer: x (B,) int32, W (K, D) fp32.
// x_emb = W[x]  =>  argmin == x  =>  quantized = W[x], diff = 0,
// loss = 0.25 * sum(W^2).  Output: [loss, quantized(B*D), diff(B*D)].
//
// Traffic-minimal scheme (LTS cap is the binding resource):
//   kernel1: build inverted index x^-1 (row -> batch positions), 16K atomics.
//   kernel2: - 128 TMA blocks zero the diff region (bulk SMEM->GMEM)
//            - 1024 row blocks: warp-per-codebook-row. Load the row ONCE
//              (4x LDG.128/lane), accumulate sum(W^2), pre-shuffle the
//              +1-shifted store tuple, then STG.128 it to every batch
//              destination of that row. Counts self-reset for graph replay.

#define NUM_K   8192
#define DIM     512
#define BATCH   16384
#define BD      (BATCH * DIM)          // 8388608 floats

#define THREADS 256
#define ZCTAS   128                    // TMA zero blocks
#define NCHUNK  1024
#define CHUNK   32768                  // bytes per bulk store (= smem buf)
#define LASTSZ  32752                  // tail chunk (total 33554416 B)
#define RBLK    (NUM_K / 8)            // 1024 row blocks, 8 warps each
#define GRID2   (ZCTAS + RBLK)
#define SLOTS   32

__device__ int          g_cnt[NUM_K];          // zero-init; self-resetting
__device__ int          g_slots[NUM_K * SLOTS];
__device__ float        g_partials[RBLK];
__device__ unsigned int g_count = 0;           // ticket; self-resetting

// ---- kernel 1: inverted index ----
__global__ void __launch_bounds__(THREADS)
vq_index_kernel(const int* __restrict__ x) {
    int b = blockIdx.x * THREADS + threadIdx.x;
    if (b < BATCH) {
        int v = __ldg(&x[b]);
        int p = atomicAdd(&g_cnt[v], 1);
        if (p < SLOTS) g_slots[v * SLOTS + p] = b;
    }
}

// ---- kernel 2: zero diff (TMA) + row-major scatter + loss ----
__global__ void __launch_bounds__(THREADS)
vq_main_kernel(const float* __restrict__ W, float* __restrict__ out) {
    __shared__ float4 zbuf[CHUNK / 16];          // 32 KB
    __shared__ float  s[THREADS];
    __shared__ bool   s_last;

    const int blk = blockIdx.x;
    const int tid = threadIdx.x;

    if (blk < ZCTAS) {
        // ---- diff zero-fill via TMA bulk stores ----
        #pragma unroll
        for (int i = 0; i < 8; ++i)
            zbuf[tid + i * THREADS] = make_float4(0.f, 0.f, 0.f, 0.f);
        __syncthreads();
        asm volatile("fence.proxy.async.shared::cta;" ::: "memory");
        if (tid == 0) {
            uint32_t sm = (uint32_t)__cvta_generic_to_shared(zbuf);
            char* gbase = (char*)(out + 4 + (size_t)BD);   // 16B aligned
            #pragma unroll
            for (int j = 0; j < 8; ++j) {
                int c = blk * 8 + j;
                uint32_t sz = (c == NCHUNK - 1) ? LASTSZ : CHUNK;
                char* g = gbase + (size_t)c * CHUNK;
                asm volatile(
                    "cp.async.bulk.global.shared::cta.bulk_group [%0], [%1], %2;"
                    :: "l"(g), "r"(sm), "r"(sz) : "memory");
            }
            asm volatile("cp.async.bulk.commit_group;" ::: "memory");
            asm volatile("cp.async.bulk.wait_group 0;" ::: "memory");
        }
        return;
    }

    // ---- row blocks: one warp per codebook row ----
    const unsigned FULL = 0xffffffffu;
    const int rb  = blk - ZCTAS;                 // 0..RBLK-1
    const int wid = tid >> 5;
    const int lid = tid & 31;
    const int row = rb * 8 + wid;

    const float4* src4 = reinterpret_cast<const float4*>(W + ((size_t)row << 9));

    // Load the row once: 4 independent LDG.128 per lane.
    float4 B0 = __ldg(&src4[lid]);
    float4 B1 = __ldg(&src4[32 + lid]);
    float4 B2 = __ldg(&src4[64 + lid]);
    float4 B3 = __ldg(&src4[96 + lid]);
    float4 E0, E1, E2;                           // lane 31 boundary vectors
    if (lid == 31) {
        E0 = __ldg(&src4[32]);
        E1 = __ldg(&src4[64]);
        E2 = __ldg(&src4[96]);
    }

    // sum of squares contribution
    float acc = B0.x*B0.x + B0.y*B0.y + B0.z*B0.z + B0.w*B0.w
              + B1.x*B1.x + B1.y*B1.y + B1.z*B1.z + B1.w*B1.w
              + B2.x*B2.x + B2.y*B2.y + B2.z*B2.z + B2.w*B2.w
              + B3.x*B3.x + B3.y*B3.y + B3.z*B3.z + B3.w*B3.w;

    // Pre-shuffle the +1-shifted store tuples (once per row):
    // chunk k (=32*IT+lid, k<127): dst[3+4k..7+4k) = (B.w, next.x, next.y, next.z)
    float4 V0, V1, V2, V3;
    #define SHIFT(B, E, V, LAST)                                              \
    {                                                                         \
        float Cx = __shfl_down_sync(FULL, (B).x, 1);                          \
        float Cy = __shfl_down_sync(FULL, (B).y, 1);                          \
        float Cz = __shfl_down_sync(FULL, (B).z, 1);                          \
        if (!(LAST) && lid == 31) { Cx = (E).x; Cy = (E).y; Cz = (E).z; }     \
        V = make_float4((B).w, Cx, Cy, Cz);                                   \
    }
    SHIFT(B0, E0, V0, 0)
    SHIFT(B1, E1, V1, 0)
    SHIFT(B2, E2, V2, 0)
    SHIFT(B3, E0, V3, 1)
    #undef SHIFT

    // Destination list for this row
    int c = 0;
    if (lid == 0) {
        c = g_cnt[row];
        g_cnt[row] = 0;                          // self-reset for graph replay
    }
    c = __shfl_sync(FULL, c, 0);
    if (c > SLOTS) c = SLOTS;

    for (int d = 0; d < c; ++d) {
        int b = __ldg(&g_slots[row * SLOTS + d]);    // broadcast load
        float* dst = out + 1 + ((size_t)b << 9);
        if (lid < 31) {
            *reinterpret_cast<float4*>(dst + 3 + 4 * lid)        = V0;
            *reinterpret_cast<float4*>(dst + 3 + 4 * (32 + lid)) = V1;
            *reinterpret_cast<float4*>(dst + 3 + 4 * (64 + lid)) = V2;
            *reinterpret_cast<float4*>(dst + 3 + 4 * (96 + lid)) = V3;
        } else {
            *reinterpret_cast<float4*>(dst + 3 + 4 * 31) = V0;
            *reinterpret_cast<float4*>(dst + 3 + 4 * 63) = V1;
            *reinterpret_cast<float4*>(dst + 3 + 4 * 95) = V2;
            dst[511] = B3.w;                     // k=127 tail scalar
        }
        if (lid == 0) { dst[0] = B0.x; dst[1] = B0.y; dst[2] = B0.z; }
    }

    // diff-region scalar edges (done once)
    if (rb == 0 && wid == 0 && lid < 4) {
        size_t idx = (lid < 3) ? ((size_t)BD + 1 + lid) : (size_t)2 * BD;
        out[idx] = 0.0f;
    }

    // ---- block reduce + ticket fold for loss ----
    s[tid] = acc;
    __syncthreads();
    #pragma unroll
    for (int o = THREADS / 2; o > 0; o >>= 1) {
        if (tid < o) s[tid] += s[tid + o];
        __syncthreads();
    }
    if (tid == 0) {
        g_partials[rb] = s[0];
        __threadfence();
        s_last = (atomicAdd(&g_count, 1u) == RBLK - 1);
    }
    __syncthreads();

    if (s_last) {
        float p = __ldcg(&g_partials[tid])       + __ldcg(&g_partials[tid + 256])
                + __ldcg(&g_partials[tid + 512]) + __ldcg(&g_partials[tid + 768]);
        s[tid] = p;
        __syncthreads();
        #pragma unroll
        for (int o = THREADS / 2; o > 0; o >>= 1) {
            if (tid < o) s[tid] += s[tid + o];
            __syncthreads();
        }
        if (tid == 0) {
            out[0] = 0.25f * s[0];
            g_count = 0;                         // reset for next replay
        }
    }
}

extern "C" void kernel_launch(void* const* d_in, const int* in_sizes, int n_in,
                              void* d_out, int out_size) {
    const int*   x = nullptr;
    const float* W = nullptr;
    if (in_sizes[0] == BATCH) {
        x = (const int*)d_in[0];
        W = (const float*)d_in[1];
    } else {
        W = (const float*)d_in[0];
        x = (const int*)d_in[1];
    }
    float* out = (float*)d_out;

    vq_index_kernel<<<BATCH / THREADS, THREADS>>>(x);
    vq_main_kernel<<<GRID2, THREADS>>>(W, out);
}

// round 8
// speedup vs baseline: 1.5152x; 1.5152x over previous
#include <cuda_runtime.h>
#include <cstdint>

// VectorQuantizer: x (B,) int32, W (K, D) fp32.
// x_emb = W[x]  =>  argmin == x  =>  quantized = W[x], diff = 0,
// loss = 0.25 * sum(W^2).  Output: [loss, quantized(B*D), diff(B*D)].
//
// Traffic-minimal scheme (W read exactly once, ~85 MB total LTS traffic):
//   kernel1: inverted index x^-1 (row -> batch positions), 16K atomics.
//   kernel2: - 128 TMA blocks zero the diff region (bulk SMEM->GMEM)
//            - 1024 row blocks, warp-per-codebook-row: prefetch count+slots
//              AND the row (all independent loads, one latency exposure),
//              accumulate sum(W^2), pre-shuffle the +1-shifted tuples, then
//              STG.128 to every destination. Counts self-reset via atomicExch.

#define NUM_K   8192
#define DIM     512
#define BATCH   16384
#define BD      (BATCH * DIM)          // 8388608 floats

#define THREADS 256
#define ZCTAS   128                    // TMA zero blocks
#define NCHUNK  2048                   // 16 chunks per zero CTA
#define CHUNK   16384                  // bytes per bulk store (= smem buf)
#define LASTSZ  16368                  // tail chunk (total 33554416 B)
#define RBLK    (NUM_K / 8)            // 1024 row blocks, 8 warps each
#define GRID2   (ZCTAS + RBLK)
#define SLOTS   32

__device__ int          g_cnt[NUM_K];          // zero-init; self-resetting
__device__ int          g_slots[NUM_K * SLOTS];
__device__ float        g_partials[RBLK];
__device__ unsigned int g_count = 0;           // ticket; self-resetting

// ---- kernel 1: inverted index ----
__global__ void __launch_bounds__(THREADS)
vq_index_kernel(const int* __restrict__ x) {
    int b = blockIdx.x * THREADS + threadIdx.x;
    if (b < BATCH) {
        int v = __ldg(&x[b]);
        int p = atomicAdd(&g_cnt[v], 1);
        if (p < SLOTS) g_slots[v * SLOTS + p] = b;
    }
}

// ---- kernel 2: zero diff (TMA) + row-major scatter + loss ----
__global__ void __launch_bounds__(THREADS)
vq_main_kernel(const float* __restrict__ W, float* __restrict__ out) {
    __shared__ float4 zbuf[CHUNK / 16];          // 16 KB
    __shared__ float  s[THREADS];
    __shared__ bool   s_last;

    const int blk = blockIdx.x;
    const int tid = threadIdx.x;

    if (blk < ZCTAS) {
        // ---- diff zero-fill via TMA bulk stores ----
        #pragma unroll
        for (int i = 0; i < 4; ++i)
            zbuf[tid + i * THREADS] = make_float4(0.f, 0.f, 0.f, 0.f);
        __syncthreads();
        asm volatile("fence.proxy.async.shared::cta;" ::: "memory");
        if (tid == 0) {
            uint32_t sm = (uint32_t)__cvta_generic_to_shared(zbuf);
            char* gbase = (char*)(out + 4 + (size_t)BD);   // 16B aligned
            #pragma unroll
            for (int j = 0; j < 16; ++j) {
                int c = blk * 16 + j;
                uint32_t sz = (c == NCHUNK - 1) ? LASTSZ : CHUNK;
                char* g = gbase + (size_t)c * CHUNK;
                asm volatile(
                    "cp.async.bulk.global.shared::cta.bulk_group [%0], [%1], %2;"
                    :: "l"(g), "r"(sm), "r"(sz) : "memory");
            }
            asm volatile("cp.async.bulk.commit_group;" ::: "memory");
            asm volatile("cp.async.bulk.wait_group 0;" ::: "memory");
        }
        return;
    }

    // ---- row blocks: one warp per codebook row ----
    const unsigned FULL = 0xffffffffu;
    const int rb  = blk - ZCTAS;                 // 0..RBLK-1
    const int wid = tid >> 5;
    const int lid = tid & 31;
    const int row = rb * 8 + wid;

    // ALL loads below are independent -> front-batched, one latency exposure.
    int cnt = 0;
    if (lid == 0) cnt = atomicExch(&g_cnt[row], 0);      // read + self-reset
    int slot = __ldg(&g_slots[row * SLOTS + lid]);       // lane d holds slot d

    const float4* src4 = reinterpret_cast<const float4*>(W + ((size_t)row << 9));
    float4 B0 = __ldg(&src4[lid]);
    float4 B1 = __ldg(&src4[32 + lid]);
    float4 B2 = __ldg(&src4[64 + lid]);
    float4 B3 = __ldg(&src4[96 + lid]);
    float4 E0, E1, E2;                           // lane 31 boundary vectors
    if (lid == 31) {
        E0 = __ldg(&src4[32]);
        E1 = __ldg(&src4[64]);
        E2 = __ldg(&src4[96]);
    }

    // sum of squares contribution
    float acc = B0.x*B0.x + B0.y*B0.y + B0.z*B0.z + B0.w*B0.w
              + B1.x*B1.x + B1.y*B1.y + B1.z*B1.z + B1.w*B1.w
              + B2.x*B2.x + B2.y*B2.y + B2.z*B2.z + B2.w*B2.w
              + B3.x*B3.x + B3.y*B3.y + B3.z*B3.z + B3.w*B3.w;

    // Pre-shuffle the +1-shifted store tuples (once per row):
    // chunk k (=32*IT+lid, k<127): dst[3+4k..7+4k) = (B.w, next.x,.y,.z)
    float4 V0, V1, V2, V3;
    #define SHIFT(B, E, V, LAST)                                              \
    {                                                                         \
        float Cx = __shfl_down_sync(FULL, (B).x, 1);                          \
        float Cy = __shfl_down_sync(FULL, (B).y, 1);                          \
        float Cz = __shfl_down_sync(FULL, (B).z, 1);                          \
        if (!(LAST) && lid == 31) { Cx = (E).x; Cy = (E).y; Cz = (E).z; }     \
        V = make_float4((B).w, Cx, Cy, Cz);                                   \
    }
    SHIFT(B0, E0, V0, 0)
    SHIFT(B1, E1, V1, 0)
    SHIFT(B2, E2, V2, 0)
    SHIFT(B3, E0, V3, 1)
    #undef SHIFT

    int c = __shfl_sync(FULL, cnt, 0);
    if (c > SLOTS) c = SLOTS;

    for (int d = 0; d < c; ++d) {
        int b = __shfl_sync(FULL, slot, d);      // register, no memory access
        float* dst = out + 1 + ((size_t)b << 9);
        if (lid < 31) {
            *reinterpret_cast<float4*>(dst + 3 + 4 * lid)        = V0;
            *reinterpret_cast<float4*>(dst + 3 + 4 * (32 + lid)) = V1;
            *reinterpret_cast<float4*>(dst + 3 + 4 * (64 + lid)) = V2;
            *reinterpret_cast<float4*>(dst + 3 + 4 * (96 + lid)) = V3;
        } else {
            *reinterpret_cast<float4*>(dst + 3 + 4 * 31) = V0;
            *reinterpret_cast<float4*>(dst + 3 + 4 * 63) = V1;
            *reinterpret_cast<float4*>(dst + 3 + 4 * 95) = V2;
            dst[511] = B3.w;                     // k=127 tail scalar
        }
        if (lid == 0) { dst[0] = B0.x; dst[1] = B0.y; dst[2] = B0.z; }
    }

    // diff-region scalar edges (done once)
    if (rb == 0 && wid == 0 && lid < 4) {
        size_t idx = (lid < 3) ? ((size_t)BD + 1 + lid) : (size_t)2 * BD;
        out[idx] = 0.0f;
    }

    // ---- block reduce + ticket fold for loss ----
    s[tid] = acc;
    __syncthreads();
    #pragma unroll
    for (int o = THREADS / 2; o > 0; o >>= 1) {
        if (tid < o) s[tid] += s[tid + o];
        __syncthreads();
    }
    if (tid == 0) {
        g_partials[rb] = s[0];
        __threadfence();
        s_last = (atomicAdd(&g_count, 1u) == RBLK - 1);
    }
    __syncthreads();

    if (s_last) {
        float p = __ldcg(&g_partials[tid])       + __ldcg(&g_partials[tid + 256])
                + __ldcg(&g_partials[tid + 512]) + __ldcg(&g_partials[tid + 768]);
        s[tid] = p;
        __syncthreads();
        #pragma unroll
        for (int o = THREADS / 2; o > 0; o >>= 1) {
            if (tid < o) s[tid] += s[tid + o];
            __syncthreads();
        }
        if (tid == 0) {
            out[0] = 0.25f * s[0];
            g_count = 0;                         // reset for next replay
        }
    }
}

extern "C" void kernel_launch(void* const* d_in, const int* in_sizes, int n_in,
                              void* d_out, int out_size) {
    const int*   x = nullptr;
    const float* W = nullptr;
    if (in_sizes[0] == BATCH) {
        x = (const int*)d_in[0];
        W = (const float*)d_in[1];
    } else {
        W = (const float*)d_in[0];
        x = (const int*)d_in[1];
    }
    float* out = (float*)d_out;

    vq_index_kernel<<<BATCH / THREADS, THREADS>>>(x);
    vq_main_kernel<<<GRID2, THREADS>>>(W, out);
}

// round 9
// speedup vs baseline: 1.6032x; 1.0581x over previous
#include <cuda_runtime.h>
#include <cstdint>

// VectorQuantizer: x (B,) int32, W (K, D) fp32.
// x_emb = W[x]  =>  argmin == x  =>  quantized = W[x], diff = 0,
// loss = 0.25 * sum(W^2).  Output: [loss, quantized(B*D), diff(B*D)].
//
// ONE kernel, traffic-minimal (~85 MB: W read once, outputs written once):
//   blk [0,128)    : TMA bulk zero of diff region (starts streaming at t=0)
//   blk [128,192)  : build inverted index x^-1 (16K spread atomics), then
//                    release ticket
//   blk [192,1216) : row blocks (warp-per-codebook-row). Spin on ticket,
//                    prefetch count+slots+row (independent), sum(W^2),
//                    pre-shuffle +1-shifted tuples, STG.128 to all dests.
// All state self-resets for graph replay.

#define NUM_K   8192
#define DIM     512
#define BATCH   16384
#define BD      (BATCH * DIM)          // 8388608 floats

#define THREADS 256
#define ZCTAS   128                    // TMA zero blocks
#define NCHUNK  2048                   // 16 chunks per zero CTA
#define CHUNK   16384                  // bytes per bulk store (= smem buf)
#define LASTSZ  16368                  // tail chunk (total 33554416 B)
#define IDXB    (BATCH / THREADS / 1)  // 64 index blocks... (16384/256)
#define RBLK    (NUM_K / 8)            // 1024 row blocks, 8 warps each
#define GRID    (ZCTAS + 64 + RBLK)    // 1216
#define SLOTS   32

__device__ int          g_cnt[NUM_K];          // zero-init; self-resetting
__device__ int          g_slots[NUM_K * SLOTS];
__device__ float        g_partials[RBLK];
__device__ unsigned int g_count = 0;           // loss ticket; self-resetting
__device__ int          g_idx_ticket = 0;      // index ticket; self-resetting

__global__ void __launch_bounds__(THREADS)
vq_fused_kernel(const int* __restrict__ x,
                const float* __restrict__ W,
                float* __restrict__ out) {
    __shared__ float4 zbuf[CHUNK / 16];          // 16 KB
    __shared__ float  s[THREADS];
    __shared__ bool   s_last;

    const int blk = blockIdx.x;
    const int tid = threadIdx.x;

    if (blk < ZCTAS) {
        // ---- diff zero-fill via TMA bulk stores (overlaps index phase) ----
        #pragma unroll
        for (int i = 0; i < 4; ++i)
            zbuf[tid + i * THREADS] = make_float4(0.f, 0.f, 0.f, 0.f);
        __syncthreads();
        asm volatile("fence.proxy.async.shared::cta;" ::: "memory");
        if (tid == 0) {
            uint32_t sm = (uint32_t)__cvta_generic_to_shared(zbuf);
            char* gbase = (char*)(out + 4 + (size_t)BD);   // 16B aligned
            #pragma unroll
            for (int j = 0; j < 16; ++j) {
                int c = blk * 16 + j;
                uint32_t sz = (c == NCHUNK - 1) ? LASTSZ : CHUNK;
                char* g = gbase + (size_t)c * CHUNK;
                asm volatile(
                    "cp.async.bulk.global.shared::cta.bulk_group [%0], [%1], %2;"
                    :: "l"(g), "r"(sm), "r"(sz) : "memory");
            }
            asm volatile("cp.async.bulk.commit_group;" ::: "memory");
            asm volatile("cp.async.bulk.wait_group 0;" ::: "memory");
        }
        return;
    }

    if (blk < ZCTAS + 64) {
        // ---- inverted index: one batch element per thread ----
        int b = (blk - ZCTAS) * THREADS + tid;
        int v = __ldg(&x[b]);
        int p = atomicAdd(&g_cnt[v], 1);
        if (p < SLOTS) g_slots[v * SLOTS + p] = b;
        __syncthreads();
        if (tid == 0) {
            __threadfence();
            atomicAdd(&g_idx_ticket, 1);
        }
        return;
    }

    // ---- row blocks: one warp per codebook row ----
    const unsigned FULL = 0xffffffffu;
    const int rb  = blk - ZCTAS - 64;            // 0..RBLK-1
    const int wid = tid >> 5;
    const int lid = tid & 31;
    const int row = rb * 8 + wid;

    // wait for the index phase (index blocks precede us in schedule order)
    if (tid == 0) {
        for (;;) {
            int t;
            asm volatile("ld.global.acquire.gpu.b32 %0, [%1];"
                         : "=r"(t) : "l"(&g_idx_ticket));
            if (t >= 64) break;
            __nanosleep(64);
        }
    }
    __syncthreads();

    // ALL loads below are independent -> front-batched, one latency exposure.
    int cnt = 0;
    if (lid == 0) cnt = atomicExch(&g_cnt[row], 0);      // read + self-reset
    int slot = __ldg(&g_slots[row * SLOTS + lid]);       // lane d holds slot d

    const float4* src4 = reinterpret_cast<const float4*>(W + ((size_t)row << 9));
    float4 B0 = __ldg(&src4[lid]);
    float4 B1 = __ldg(&src4[32 + lid]);
    float4 B2 = __ldg(&src4[64 + lid]);
    float4 B3 = __ldg(&src4[96 + lid]);
    float4 E0, E1, E2;                           // lane 31 boundary vectors
    if (lid == 31) {
        E0 = __ldg(&src4[32]);
        E1 = __ldg(&src4[64]);
        E2 = __ldg(&src4[96]);
    }

    // sum of squares contribution
    float acc = B0.x*B0.x + B0.y*B0.y + B0.z*B0.z + B0.w*B0.w
              + B1.x*B1.x + B1.y*B1.y + B1.z*B1.z + B1.w*B1.w
              + B2.x*B2.x + B2.y*B2.y + B2.z*B2.z + B2.w*B2.w
              + B3.x*B3.x + B3.y*B3.y + B3.z*B3.z + B3.w*B3.w;

    // Pre-shuffle the +1-shifted store tuples (once per row):
    // chunk k (=32*IT+lid, k<127): dst[3+4k..7+4k) = (B.w, next.x,.y,.z)
    float4 V0, V1, V2, V3;
    #define SHIFT(B, E, V, LAST)                                              \
    {                                                                         \
        float Cx = __shfl_down_sync(FULL, (B).x, 1);                          \
        float Cy = __shfl_down_sync(FULL, (B).y, 1);                          \
        float Cz = __shfl_down_sync(FULL, (B).z, 1);                          \
        if (!(LAST) && lid == 31) { Cx = (E).x; Cy = (E).y; Cz = (E).z; }     \
        V = make_float4((B).w, Cx, Cy, Cz);                                   \
    }
    SHIFT(B0, E0, V0, 0)
    SHIFT(B1, E1, V1, 0)
    SHIFT(B2, E2, V2, 0)
    SHIFT(B3, E0, V3, 1)
    #undef SHIFT

    int c = __shfl_sync(FULL, cnt, 0);
    if (c > SLOTS) c = SLOTS;

    for (int d = 0; d < c; ++d) {
        int b = __shfl_sync(FULL, slot, d);      // register, no memory access
        float* dst = out + 1 + ((size_t)b << 9);
        if (lid < 31) {
            *reinterpret_cast<float4*>(dst + 3 + 4 * lid)        = V0;
            *reinterpret_cast<float4*>(dst + 3 + 4 * (32 + lid)) = V1;
            *reinterpret_cast<float4*>(dst + 3 + 4 * (64 + lid)) = V2;
            *reinterpret_cast<float4*>(dst + 3 + 4 * (96 + lid)) = V3;
        } else {
            *reinterpret_cast<float4*>(dst + 3 + 4 * 31) = V0;
            *reinterpret_cast<float4*>(dst + 3 + 4 * 63) = V1;
            *reinterpret_cast<float4*>(dst + 3 + 4 * 95) = V2;
            dst[511] = B3.w;                     // k=127 tail scalar
        }
        if (lid == 0) { dst[0] = B0.x; dst[1] = B0.y; dst[2] = B0.z; }
    }

    // diff-region scalar edges (done once)
    if (rb == 0 && wid == 0 && lid < 4) {
        size_t idx = (lid < 3) ? ((size_t)BD + 1 + lid) : (size_t)2 * BD;
        out[idx] = 0.0f;
    }

    // ---- block reduce + ticket fold for loss ----
    s[tid] = acc;
    __syncthreads();
    #pragma unroll
    for (int o = THREADS / 2; o > 0; o >>= 1) {
        if (tid < o) s[tid] += s[tid + o];
        __syncthreads();
    }
    if (tid == 0) {
        g_partials[rb] = s[0];
        __threadfence();
        s_last = (atomicAdd(&g_count, 1u) == RBLK - 1);
    }
    __syncthreads();

    if (s_last) {
        float p = __ldcg(&g_partials[tid])       + __ldcg(&g_partials[tid + 256])
                + __ldcg(&g_partials[tid + 512]) + __ldcg(&g_partials[tid + 768]);
        s[tid] = p;
        __syncthreads();
        #pragma unroll
        for (int o = THREADS / 2; o > 0; o >>= 1) {
            if (tid < o) s[tid] += s[tid + o];
            __syncthreads();
        }
        if (tid == 0) {
            out[0] = 0.25f * s[0];
            g_count = 0;                         // reset for next replay
            g_idx_ticket = 0;                    // reset for next replay
        }
    }
}

extern "C" void kernel_launch(void* const* d_in, const int* in_sizes, int n_in,
                              void* d_out, int out_size) {
    const int*   x = nullptr;
    const float* W = nullptr;
    if (in_sizes[0] == BATCH) {
        x = (const int*)d_in[0];
        W = (const float*)d_in[1];
    } else {
        W = (const float*)d_in[0];
        x = (const int*)d_in[1];
    }
    float* out = (float*)d_out;
    vq_fused_kernel<<<GRID, THREADS>>>(x, W, out);
}

// round 10
// speedup vs baseline: 1.6791x; 1.0473x over previous
#include <cuda_runtime.h>
#include <cstdint>

// VectorQuantizer: x (B,) int32, W (K, D) fp32.
// x_emb = W[x]  =>  argmin == x  =>  quantized = W[x], diff = 0,
// loss = 0.25 * sum(W^2).  Output: [loss, quantized(B*D), diff(B*D)].
//
// ONE kernel, traffic-minimal (~85 MB: W read once, outputs written once):
//   blk [0,128)    : TMA bulk zero of diff region (streams from t=0)
//   blk [128,192)  : inverted index x^-1 (16K spread atomics) -> ticket
//   blk [192,1216) : row blocks (warp-per-codebook-row):
//                    (1) PREFETCH row + sumsq + shuffle-shift  (index-indep!)
//                    (2) wait ticket (already released by now)
//                    (3) read count+slots (one short exposure)
//                    (4) STG.128 the pre-shifted tuples to every destination
// All state self-resets for graph replay.

#define NUM_K   8192
#define DIM     512
#define BATCH   16384
#define BD      (BATCH * DIM)          // 8388608 floats

#define THREADS 256
#define ZCTAS   128                    // TMA zero blocks
#define NCHUNK  2048                   // 16 chunks per zero CTA
#define CHUNK   16384                  // bytes per bulk store (= smem buf)
#define LASTSZ  16368                  // tail chunk (total 33554416 B)
#define RBLK    (NUM_K / 8)            // 1024 row blocks, 8 warps each
#define GRID    (ZCTAS + 64 + RBLK)    // 1216
#define SLOTS   32

__device__ int          g_cnt[NUM_K];          // zero-init; self-resetting
__device__ int          g_slots[NUM_K * SLOTS];
__device__ float        g_partials[RBLK];
__device__ unsigned int g_count = 0;           // loss ticket; self-resetting
__device__ int          g_idx_ticket = 0;      // index ticket; self-resetting

__global__ void __launch_bounds__(THREADS)
vq_fused_kernel(const int* __restrict__ x,
                const float* __restrict__ W,
                float* __restrict__ out) {
    __shared__ float4 zbuf[CHUNK / 16];          // 16 KB
    __shared__ float  s[THREADS];
    __shared__ bool   s_last;

    const int blk = blockIdx.x;
    const int tid = threadIdx.x;

    if (blk < ZCTAS) {
        // ---- diff zero-fill via TMA bulk stores (overlaps everything) ----
        #pragma unroll
        for (int i = 0; i < 4; ++i)
            zbuf[tid + i * THREADS] = make_float4(0.f, 0.f, 0.f, 0.f);
        __syncthreads();
        asm volatile("fence.proxy.async.shared::cta;" ::: "memory");
        if (tid == 0) {
            uint32_t sm = (uint32_t)__cvta_generic_to_shared(zbuf);
            char* gbase = (char*)(out + 4 + (size_t)BD);   // 16B aligned
            #pragma unroll
            for (int j = 0; j < 16; ++j) {
                int c = blk * 16 + j;
                uint32_t sz = (c == NCHUNK - 1) ? LASTSZ : CHUNK;
                char* g = gbase + (size_t)c * CHUNK;
                asm volatile(
                    "cp.async.bulk.global.shared::cta.bulk_group [%0], [%1], %2;"
                    :: "l"(g), "r"(sm), "r"(sz) : "memory");
            }
            asm volatile("cp.async.bulk.commit_group;" ::: "memory");
            asm volatile("cp.async.bulk.wait_group 0;" ::: "memory");
        }
        return;
    }

    if (blk < ZCTAS + 64) {
        // ---- inverted index: one batch element per thread ----
        int b = (blk - ZCTAS) * THREADS + tid;
        int v = __ldg(&x[b]);
        int p = atomicAdd(&g_cnt[v], 1);
        if (p < SLOTS) g_slots[v * SLOTS + p] = b;
        __syncthreads();
        if (tid == 0) {
            __threadfence();
            atomicAdd(&g_idx_ticket, 1);
        }
        return;
    }

    // ---- row blocks: one warp per codebook row ----
    const unsigned FULL = 0xffffffffu;
    const int rb  = blk - ZCTAS - 64;            // 0..RBLK-1
    const int wid = tid >> 5;
    const int lid = tid & 31;
    const int row = rb * 8 + wid;

    // (1) PREFETCH the row immediately — independent of the index phase.
    const float4* src4 = reinterpret_cast<const float4*>(W + ((size_t)row << 9));
    float4 B0 = __ldg(&src4[lid]);
    float4 B1 = __ldg(&src4[32 + lid]);
    float4 B2 = __ldg(&src4[64 + lid]);
    float4 B3 = __ldg(&src4[96 + lid]);
    float4 E0, E1, E2;                           // lane 31 boundary vectors
    if (lid == 31) {
        E0 = __ldg(&src4[32]);
        E1 = __ldg(&src4[64]);
        E2 = __ldg(&src4[96]);
    }

    // sum of squares contribution
    float acc = B0.x*B0.x + B0.y*B0.y + B0.z*B0.z + B0.w*B0.w
              + B1.x*B1.x + B1.y*B1.y + B1.z*B1.z + B1.w*B1.w
              + B2.x*B2.x + B2.y*B2.y + B2.z*B2.z + B2.w*B2.w
              + B3.x*B3.x + B3.y*B3.y + B3.z*B3.z + B3.w*B3.w;

    // Pre-shuffle the +1-shifted store tuples (once per row):
    // chunk k (=32*IT+lid, k<127): dst[3+4k..7+4k) = (B.w, next.x,.y,.z)
    float4 V0, V1, V2, V3;
    #define SHIFT(B, E, V, LAST)                                              \
    {                                                                         \
        float Cx = __shfl_down_sync(FULL, (B).x, 1);                          \
        float Cy = __shfl_down_sync(FULL, (B).y, 1);                          \
        float Cz = __shfl_down_sync(FULL, (B).z, 1);                          \
        if (!(LAST) && lid == 31) { Cx = (E).x; Cy = (E).y; Cz = (E).z; }     \
        V = make_float4((B).w, Cx, Cy, Cz);                                   \
    }
    SHIFT(B0, E0, V0, 0)
    SHIFT(B1, E1, V1, 0)
    SHIFT(B2, E2, V2, 0)
    SHIFT(B3, E0, V3, 1)
    #undef SHIFT

    // (2) wait for the index phase (normally already complete by now)
    if (tid == 0) {
        for (;;) {
            int t;
            asm volatile("ld.global.acquire.gpu.b32 %0, [%1];"
                         : "=r"(t) : "l"(&g_idx_ticket));
            if (t >= 64) break;
            __nanosleep(32);
        }
    }
    __syncthreads();

    // (3) one short exposure: count (read+reset) and slots (L2-coherent)
    int cnt = 0;
    if (lid == 0) cnt = atomicExch(&g_cnt[row], 0);
    int slot = __ldcg(&g_slots[row * SLOTS + lid]);      // lane d holds slot d

    int c = __shfl_sync(FULL, cnt, 0);
    if (c > SLOTS) c = SLOTS;

    // (4) fire-and-forget stores to every destination of this row
    for (int d = 0; d < c; ++d) {
        int b = __shfl_sync(FULL, slot, d);      // register, no memory access
        float* dst = out + 1 + ((size_t)b << 9);
        if (lid < 31) {
            *reinterpret_cast<float4*>(dst + 3 + 4 * lid)        = V0;
            *reinterpret_cast<float4*>(dst + 3 + 4 * (32 + lid)) = V1;
            *reinterpret_cast<float4*>(dst + 3 + 4 * (64 + lid)) = V2;
            *reinterpret_cast<float4*>(dst + 3 + 4 * (96 + lid)) = V3;
        } else {
            *reinterpret_cast<float4*>(dst + 3 + 4 * 31) = V0;
            *reinterpret_cast<float4*>(dst + 3 + 4 * 63) = V1;
            *reinterpret_cast<float4*>(dst + 3 + 4 * 95) = V2;
            dst[511] = B3.w;                     // k=127 tail scalar
        }
        if (lid == 0) { dst[0] = B0.x; dst[1] = B0.y; dst[2] = B0.z; }
    }

    // diff-region scalar edges (done once)
    if (rb == 0 && wid == 0 && lid < 4) {
        size_t idx = (lid < 3) ? ((size_t)BD + 1 + lid) : (size_t)2 * BD;
        out[idx] = 0.0f;
    }

    // ---- block reduce + ticket fold for loss ----
    s[tid] = acc;
    __syncthreads();
    #pragma unroll
    for (int o = THREADS / 2; o > 0; o >>= 1) {
        if (tid < o) s[tid] += s[tid + o];
        __syncthreads();
    }
    if (tid == 0) {
        g_partials[rb] = s[0];
        __threadfence();
        s_last = (atomicAdd(&g_count, 1u) == RBLK - 1);
    }
    __syncthreads();

    if (s_last) {
        float p = __ldcg(&g_partials[tid])       + __ldcg(&g_partials[tid + 256])
                + __ldcg(&g_partials[tid + 512]) + __ldcg(&g_partials[tid + 768]);
        s[tid] = p;
        __syncthreads();
        #pragma unroll
        for (int o = THREADS / 2; o > 0; o >>= 1) {
            if (tid < o) s[tid] += s[tid + o];
            __syncthreads();
        }
        if (tid == 0) {
            out[0] = 0.25f * s[0];
            g_count = 0;                         // reset for next replay
            g_idx_ticket = 0;                    // reset for next replay
        }
    }
}

extern "C" void kernel_launch(void* const* d_in, const int* in_sizes, int n_in,
                              void* d_out, int out_size) {
    const int*   x = nullptr;
    const float* W = nullptr;
    if (in_sizes[0] == BATCH) {
        x = (const int*)d_in[0];
        W = (const float*)d_in[1];
    } else {
        W = (const float*)d_in[0];
        x = (const int*)d_in[1];
    }
    float* out = (float*)d_out;
    vq_fused_kernel<<<GRID, THREADS>>>(x, W, out);
}

// round 11
// speedup vs baseline: 1.8826x; 1.1212x over previous
#include <cuda_runtime.h>
#include <cstdint>

// VectorQuantizer: x (B,) int32, W (K, D) fp32.
// x_emb = W[x]  =>  argmin_k ||W[x_i]-W[k]||^2 == x_i  =>
//   quantized = W[x], diff = 0, loss = 0.25 * sum(W^2).
// Output layout: [loss, quantized(B*D), diff(B*D)]  (out_size = 1 + 2*B*D).
//
// Block classes (zero CTAs first so their TMA bulk stores overlap everything):
//   [0, ZCTAS)              diff zero-fill via cp.async.bulk SMEM->GMEM
//   [ZCTAS, ZCTAS+SUMB)     sum(W^2); last-arriving block folds -> out[0]
//   [ZCTAS+SUMB, GRID)      gather: warp-per-row, LDG.128 + SHFL + STG.128
//
// This configuration runs at the measured LTS throughput cap (~7.5 GB/us on
// ~117 MB of L2 traffic) — champion configuration (R6).

#define NUM_K   8192
#define DIM     512
#define BATCH   16384
#define WSIZE   (NUM_K * DIM)          // 4194304 floats
#define BD      (BATCH * DIM)          // 8388608 floats

#define THREADS 256
#define ZCTAS   128                    // TMA zero blocks
#define NCHUNK  1024                   // 8 chunks per zero CTA
#define CHUNK   32768                  // bytes per bulk store (= smem buf)
#define LASTSZ  32752                  // tail chunk (total 33554416 B)
#define SUMB    512                    // 512*256*8 float4 = WSIZE/4
#define QBLK    2048                   // 8 warps/block, 1 row/warp
#define GRID    (ZCTAS + SUMB + QBLK)

__device__ float        g_partials[SUMB];
__device__ unsigned int g_count = 0;   // self-resetting ticket (graph-replay safe)

__global__ void __launch_bounds__(THREADS)
vq_fused_kernel(const int* __restrict__ x,
                const float* __restrict__ W,
                float* __restrict__ out) {
    __shared__ float4 zbuf[CHUNK / 16];          // 32 KB
    __shared__ float  s[THREADS];
    __shared__ bool   s_last;

    const int blk = blockIdx.x;
    const int tid = threadIdx.x;

    if (blk < ZCTAS) {
        // ---- diff zero-fill via TMA bulk stores ----
        #pragma unroll
        for (int i = 0; i < 8; ++i)
            zbuf[tid + i * THREADS] = make_float4(0.f, 0.f, 0.f, 0.f);
        __syncthreads();
        asm volatile("fence.proxy.async.shared::cta;" ::: "memory");
        if (tid == 0) {
            uint32_t sm = (uint32_t)__cvta_generic_to_shared(zbuf);
            char* gbase = (char*)(out + 4 + (size_t)BD);   // 16B aligned
            #pragma unroll
            for (int j = 0; j < 8; ++j) {
                int c = blk * 8 + j;
                uint32_t sz = (c == NCHUNK - 1) ? LASTSZ : CHUNK;
                char* g = gbase + (size_t)c * CHUNK;
                asm volatile(
                    "cp.async.bulk.global.shared::cta.bulk_group [%0], [%1], %2;"
                    :: "l"(g), "r"(sm), "r"(sz) : "memory");
            }
            asm volatile("cp.async.bulk.commit_group;" ::: "memory");
            asm volatile("cp.async.bulk.wait_group 0;" ::: "memory");
        }
    } else if (blk < ZCTAS + SUMB) {
        // ---- sum of squares over W: 8 front-batched float4 loads ----
        const int sb = blk - ZCTAS;
        const float4* W4 = reinterpret_cast<const float4*>(W);
        size_t base = (size_t)sb * (THREADS * 8) + tid;
        float acc = 0.0f;
        #pragma unroll
        for (int i = 0; i < 8; ++i) {
            float4 v = W4[base + (size_t)i * THREADS];
            acc += v.x * v.x + v.y * v.y + v.z * v.z + v.w * v.w;
        }

        s[tid] = acc;
        __syncthreads();
        #pragma unroll
        for (int o = THREADS / 2; o > 0; o >>= 1) {
            if (tid < o) s[tid] += s[tid + o];
            __syncthreads();
        }

        if (tid == 0) {
            g_partials[sb] = s[0];
            __threadfence();
            s_last = (atomicAdd(&g_count, 1u) == SUMB - 1);
        }
        __syncthreads();

        if (s_last) {
            float p = __ldcg(&g_partials[tid]) + __ldcg(&g_partials[tid + 256]);
            s[tid] = p;
            __syncthreads();
            #pragma unroll
            for (int o = THREADS / 2; o > 0; o >>= 1) {
                if (tid < o) s[tid] += s[tid + o];
                __syncthreads();
            }
            if (tid == 0) {
                out[0] = 0.25f * s[0];
                g_count = 0;           // reset for next graph replay
            }
        }
    } else {
        // ---- gather quantized = W[x]: one warp per batch row ----
        const unsigned FULL = 0xffffffffu;
        const int q   = blk - ZCTAS - SUMB;
        const int wid = tid >> 5;
        const int lid = tid & 31;
        const int b   = q * 8 + wid;                     // batch row

        int row = 0;
        if (lid == 0) row = __ldg(&x[b]);
        row = __shfl_sync(FULL, row, 0);

        const float4* src4 = reinterpret_cast<const float4*>(W + ((size_t)row << 9));
        float*        dst  = out + 1 + ((size_t)b << 9);

        // All loads independent (front-batched by ptxas):
        float4 B0 = __ldg(&src4[lid]);
        float4 B1 = __ldg(&src4[32 + lid]);
        float4 B2 = __ldg(&src4[64 + lid]);
        float4 B3 = __ldg(&src4[96 + lid]);
        float4 E0, E1, E2;                // lane 31's group-boundary vectors
        if (lid == 31) {
            E0 = __ldg(&src4[32]);
            E1 = __ldg(&src4[64]);
            E2 = __ldg(&src4[96]);
        }

        // chunk k (0..126): dst[3+4k..7+4k) = (src4[k].w, src4[k+1].xyz)
        #define EMIT(IT, B, E, LAST)                                          \
        {                                                                     \
            float Cx = __shfl_down_sync(FULL, (B).x, 1);                      \
            float Cy = __shfl_down_sync(FULL, (B).y, 1);                      \
            float Cz = __shfl_down_sync(FULL, (B).z, 1);                      \
            if (!(LAST) && lid == 31) { Cx = (E).x; Cy = (E).y; Cz = (E).z; } \
            int k = 32 * (IT) + lid;                                          \
            if (k < 127) {                                                    \
                float4 v = make_float4((B).w, Cx, Cy, Cz);                    \
                *reinterpret_cast<float4*>(dst + 3 + 4 * k) = v;              \
            }                                                                 \
        }
        EMIT(0, B0, E0, 0)
        EMIT(1, B1, E1, 0)
        EMIT(2, B2, E2, 0)
        EMIT(3, B3, E0, 1)
        #undef EMIT

        // row edges straight from registers
        if (lid == 0) { dst[0] = B0.x; dst[1] = B0.y; dst[2] = B0.z; }
        if (lid == 31) dst[511] = B3.w;

        // global scalar edges of the diff region (done once)
        if (q == 0 && wid == 0 && lid < 4) {
            size_t idx = (lid < 3) ? ((size_t)BD + 1 + lid) : (size_t)2 * BD;
            out[idx] = 0.0f;
        }
    }
}

extern "C" void kernel_launch(void* const* d_in, const int* in_sizes, int n_in,
                              void* d_out, int out_size) {
    const int*   x = nullptr;
    const float* W = nullptr;
    if (in_sizes[0] == BATCH) {
        x = (const int*)d_in[0];
        W = (const float*)d_in[1];
    } else {
        W = (const float*)d_in[0];
        x = (const int*)d_in[1];
    }
    float* out = (float*)d_out;
    vq_fused_kernel<<<GRID, THREADS>>>(x, W, out);
}